// round 1
// baseline (speedup 1.0000x reference)
#include <cuda_runtime.h>
#include <math.h>

#define D1 768
#define D2 768
#define D2R 385
#define NF (D1*D2R)     // 295680
#define KN_ 4
#define B_ 8
#define C_ 256
#define HW_ 64

// ---------------- scratch (static device globals; no allocation) ----------
__device__ float  g_att[B_*KN_];
__device__ float2 g_tw[D1];                 // (cos, sin) of 2*pi*j/768
__device__ float  g_Gr[KN_][NF];            // scattered freq map, real  [p][q]
__device__ float  g_Gi[KN_][NF];            //                      imag
__device__ float  g_Yr[KN_][NF];            // after axis-0 ifft (scaled) [m][q]
__device__ float  g_Yi[KN_][NF];
__device__ float  g_S [KN_][D1*D2];         // spatial weights [m][t]
__device__ float  g_Wb[B_][C_*C_*9];        // per-batch conv W, K-major: [(i*9+st)*256 + o]

// ---------------- setup: attention + twiddle table -------------------------
__global__ void k_setup(const float* __restrict__ katt) {
    int j = threadIdx.x;
    if (j < D1) {
        double ang = 2.0 * M_PI * (double)j / (double)D1;
        g_tw[j] = make_float2((float)cos(ang), (float)sin(ang));
    }
    if (j < B_*KN_) {
        // sigmoid(a/1.0) * 2/4
        g_att[j] = 0.5f / (1.0f + expf(-katt[j]));
    }
}

// ---------------- scatter dft_weight into dense rfft2 grid -----------------
__global__ void k_scatter(const float* __restrict__ dw,
                          const int*   __restrict__ fh,
                          const int*   __restrict__ fw) {
    int n = blockIdx.x * 256 + threadIdx.x;
    if (n >= NF) return;
    int pos = fh[n] * D2R + fw[n];
    const float2* dw2 = (const float2*)dw;
#pragma unroll
    for (int k = 0; k < KN_; ++k) {
        float2 v = dw2[k*NF + n];
        g_Gr[k][pos] = v.x;
        g_Gi[k][pos] = v.y;
    }
}

// ---------------- axis-0 complex inverse DFT (length 768) ------------------
// Y[m][q] = scale(q) * sum_p G[p][q] * exp(+2*pi*i*m*p/768)
// scale folds 1/(768*768) and rfft fold weight wq (and zeroes imag at q=0,384)
__global__ void __launch_bounds__(256) k_dftP() {
    __shared__ float2 stw[D1];
    __shared__ float  sGr[32][33];
    __shared__ float  sGi[32][33];
    int k  = blockIdx.z;
    int q0 = blockIdx.x * 32;
    int m0 = blockIdx.y * 64;
    int tx = threadIdx.x, ty = threadIdx.y;
    int tid = ty*32 + tx;
    for (int j = tid; j < D1; j += 256) stw[j] = g_tw[j];

    int q = q0 + tx;
    bool qv = (q < D2R);

    float accr[8], acci[8];
    int   jm[8], ms[8];
#pragma unroll
    for (int mm = 0; mm < 8; ++mm) {
        accr[mm] = 0.f; acci[mm] = 0.f;
        ms[mm] = m0 + ty*8 + mm;
        jm[mm] = 0;                       // (m*0) % 768
    }

    for (int p0 = 0; p0 < D1; p0 += 32) {
        __syncthreads();
#pragma unroll
        for (int r = 0; r < 4; ++r) {
            int pl = ty*4 + r;            // 0..31
            int p  = p0 + pl;
            sGr[pl][tx] = qv ? g_Gr[k][p*D2R + q] : 0.f;
            sGi[pl][tx] = qv ? g_Gi[k][p*D2R + q] : 0.f;
        }
        __syncthreads();
#pragma unroll
        for (int pl = 0; pl < 32; ++pl) {
            float gr = sGr[pl][tx];
            float gi = sGi[pl][tx];
#pragma unroll
            for (int mm = 0; mm < 8; ++mm) {
                float2 cs = stw[jm[mm]];          // warp-uniform -> broadcast
                accr[mm] += cs.x*gr - cs.y*gi;
                acci[mm] += cs.x*gi + cs.y*gr;
                jm[mm] += ms[mm];
                if (jm[mm] >= D1) jm[mm] -= D1;
            }
        }
    }

    if (qv) {
        bool edge = (q == 0) || (q == 384);
        float sc  = (edge ? 1.f : 2.f) * (1.f/((float)D1*(float)D2));
        float sci = edge ? 0.f : sc;      // imag of DC/Nyquist is ignored by irfft
#pragma unroll
        for (int mm = 0; mm < 8; ++mm) {
            g_Yr[k][ms[mm]*D2R + q] = accr[mm]*sc;
            g_Yi[k][ms[mm]*D2R + q] = acci[mm]*sci;
        }
    }
}

// ---------------- axis-1 irfft (385 -> 768 real) ---------------------------
// S[m][t] = sum_q ( Yr[m][q]*cos(2*pi*q*t/768) - Yi[m][q]*sin(...) )
__global__ void __launch_bounds__(256) k_irfftQ() {
    __shared__ float2 stw[D1];
    __shared__ __align__(16) float sYr[32][68];
    __shared__ __align__(16) float sYi[32][68];
    int k  = blockIdx.z;
    int t0 = blockIdx.x * 32;
    int m0 = blockIdx.y * 64;
    int tx = threadIdx.x, ty = threadIdx.y;
    int tid = ty*32 + tx;
    for (int j = tid; j < D1; j += 256) stw[j] = g_tw[j];

    int t = t0 + tx;
    float acc[8];
#pragma unroll
    for (int mm = 0; mm < 8; ++mm) acc[mm] = 0.f;
    int jq = 0;                           // (q*t) % 768, q starts at 0

    for (int q0 = 0; q0 < D2R; q0 += 32) {
        __syncthreads();
#pragma unroll
        for (int r = 0; r < 8; ++r) {
            int ml = ty*8 + r;            // 0..63
            int q  = q0 + tx;
            bool v = (q < D2R);
            sYr[tx][ml] = v ? g_Yr[k][(m0+ml)*D2R + q] : 0.f;
            sYi[tx][ml] = v ? g_Yi[k][(m0+ml)*D2R + q] : 0.f;
        }
        __syncthreads();
#pragma unroll
        for (int ql = 0; ql < 32; ++ql) {
            float2 cs = stw[jq];
            const float4* pr = (const float4*)&sYr[ql][ty*8];
            const float4* pi = (const float4*)&sYi[ql][ty*8];
            float4 r0 = pr[0], r1 = pr[1];
            float4 i0 = pi[0], i1 = pi[1];
            acc[0] += cs.x*r0.x - cs.y*i0.x;
            acc[1] += cs.x*r0.y - cs.y*i0.y;
            acc[2] += cs.x*r0.z - cs.y*i0.z;
            acc[3] += cs.x*r0.w - cs.y*i0.w;
            acc[4] += cs.x*r1.x - cs.y*i1.x;
            acc[5] += cs.x*r1.y - cs.y*i1.y;
            acc[6] += cs.x*r1.z - cs.y*i1.z;
            acc[7] += cs.x*r1.w - cs.y*i1.w;
            jq += t;
            if (jq >= D1) jq -= D1;
        }
    }
#pragma unroll
    for (int mm = 0; mm < 8; ++mm)
        g_S[k][(m0 + ty*8 + mm)*D2 + t] = acc[mm];
}

// ---------------- combine per-batch weights (K-major for conv) -------------
// g_Wb[b][(i*9+st)*256 + o] = sum_k att[b][k] * S_k[o*3+s][i*3+t]
__global__ void k_combine() {
    int id = blockIdx.x * 256 + threadIdx.x;   // 0 .. 8*256*9*256-1
    int o  = id & 255;
    int r  = id >> 8;        // = b*2304 + i*9 + st
    int st = r % 9;
    int r2 = r / 9;
    int i  = r2 & 255;
    int b  = r2 >> 8;
    int s  = st / 3, tt = st % 3;
    int sidx = (o*3 + s)*D2 + i*3 + tt;
    float v = 0.f;
#pragma unroll
    for (int k = 0; k < KN_; ++k)
        v += g_att[b*KN_ + k] * g_S[k][sidx];
    g_Wb[b][(i*9 + st)*256 + o] = v;
}

// ---------------- grouped 3x3 conv, per batch ------------------------------
// block: 64 out-channels x (4x16) pixel tile; thread: 4 o x 4 pix
__global__ void __launch_bounds__(256) k_conv(const float* __restrict__ xin,
                                              float* __restrict__ out) {
    __shared__ __align__(16) float sX[8][6][20];   // 8 in-ch x (4+2) x (16+2), padded
    __shared__ __align__(16) float sW[8][9][64];   // [i][st][o]
    int b    = blockIdx.z;
    int o0   = blockIdx.y * 64;
    int tile = blockIdx.x;               // 0..63
    int y0 = (tile >> 2) * 4;
    int x0 = (tile & 3) * 16;
    int tid = threadIdx.x;
    int to = tid >> 4;                   // 0..15 -> 4 o's each
    int tp = tid & 15;                   // 0..15 -> 4 pix each
    int py = tp >> 2;                    // 0..3
    int px = (tp & 3) * 4;               // 0,4,8,12

    const float* xb = xin + (size_t)b * C_ * HW_ * HW_;
    const float* wb = g_Wb[b];

    float acc[4][4];
#pragma unroll
    for (int a = 0; a < 4; ++a)
#pragma unroll
        for (int j = 0; j < 4; ++j) acc[a][j] = 0.f;

    for (int i0 = 0; i0 < C_; i0 += 8) {
        __syncthreads();
        // load x patch: 8 x 6 x 18 = 864 elements
        for (int idx = tid; idx < 8*6*18; idx += 256) {
            int il = idx / 108;
            int r  = idx % 108;
            int ry = r / 18, rx = r % 18;
            int iy = y0 + ry - 1, ix = x0 + rx - 1;
            float v = 0.f;
            if (iy >= 0 && iy < HW_ && ix >= 0 && ix < HW_)
                v = xb[(i0 + il)*(HW_*HW_) + iy*HW_ + ix];
            sX[il][ry][rx] = v;
        }
        // load weights: 8*9*64 = 4608 elements, coalesced (K-major layout)
        float* sWf = &sW[0][0][0];
        for (int idx = tid; idx < 8*9*64; idx += 256) {
            int ol = idx & 63;
            int r  = idx >> 6;           // i*9 + st
            sWf[idx] = wb[((i0 + r/9)*9 + (r%9))*256 + o0 + ol];
        }
        __syncthreads();
#pragma unroll
        for (int il = 0; il < 8; ++il) {
            float xr[3][6];
#pragma unroll
            for (int dy = 0; dy < 3; ++dy)
#pragma unroll
                for (int j = 0; j < 6; ++j)
                    xr[dy][j] = sX[il][py + dy][px + j];
#pragma unroll
            for (int dy = 0; dy < 3; ++dy)
#pragma unroll
                for (int dx = 0; dx < 3; ++dx) {
                    float4 w4 = *(const float4*)&sW[il][dy*3 + dx][to*4];
#pragma unroll
                    for (int j = 0; j < 4; ++j) {
                        float xv = xr[dy][j + dx];
                        acc[0][j] += w4.x * xv;
                        acc[1][j] += w4.y * xv;
                        acc[2][j] += w4.z * xv;
                        acc[3][j] += w4.w * xv;
                    }
                }
        }
    }

    float* ob = out + (size_t)b * C_ * HW_ * HW_;
#pragma unroll
    for (int oo = 0; oo < 4; ++oo) {
        int o = o0 + to*4 + oo;
        float4 v = make_float4(acc[oo][0], acc[oo][1], acc[oo][2], acc[oo][3]);
        *(float4*)&ob[o*(HW_*HW_) + (y0 + py)*HW_ + x0 + px] = v;
    }
}

// ---------------- launch ----------------------------------------------------
extern "C" void kernel_launch(void* const* d_in, const int* in_sizes, int n_in,
                              void* d_out, int out_size) {
    const float* x    = (const float*)d_in[0];
    const float* dw   = (const float*)d_in[1];
    const float* katt = (const float*)d_in[2];
    const int*   fh   = (const int*)d_in[3];
    const int*   fw   = (const int*)d_in[4];
    float* out = (float*)d_out;

    k_setup  <<<1, 768>>>(katt);
    k_scatter<<<(NF + 255)/256, 256>>>(dw, fh, fw);
    k_dftP   <<<dim3(13, 12, KN_), dim3(32, 8)>>>();
    k_irfftQ <<<dim3(24, 12, KN_), dim3(32, 8)>>>();
    k_combine<<<(B_*C_*C_*9)/256, 256>>>();
    k_conv   <<<dim3(64, 4, B_), 256>>>(x, out);
}